// round 1
// baseline (speedup 1.0000x reference)
#include <cuda_runtime.h>
#include <math.h>

// Problem constants
#define D_DIM 1536
#define E_NUM 64
#define H_DIM 384
#define TOPK  8
#define CAP   1024
#define T_NUM 4096

// ---------------- scratch (static device globals; no allocations) ----------
__device__ __align__(16) int   g_counts[E_NUM];
__device__ __align__(16) int   g_slot_token[E_NUM * CAP];
__device__ __align__(16) float g_slot_weight[E_NUM * CAP];
__device__ __align__(16) float g_act[(size_t)E_NUM * CAP * H_DIM]; // ~100 MB

// ---------------- kernel 1: zero out + counters ----------------------------
__global__ void zero_kernel(float* __restrict__ out) {
    int i = blockIdx.x * blockDim.x + threadIdx.x;
    if (blockIdx.x == 0 && threadIdx.x < E_NUM) g_counts[threadIdx.x] = 0;
    const int n4 = T_NUM * D_DIM / 4;
    float4 z = make_float4(0.f, 0.f, 0.f, 0.f);
    for (int idx = i; idx < n4; idx += gridDim.x * blockDim.x)
        ((float4*)out)[idx] = z;
}

// ---------------- kernel 2: router (logits + softmax + top8 + dispatch) ----
// 8 tokens per block, 256 threads. Dynamic smem: xs[8][D] + logits[8][64].
extern __shared__ float s_router[];

__global__ __launch_bounds__(256) void router_kernel(
    const float* __restrict__ x, const float* __restrict__ gate_w)
{
    float (*xs)[D_DIM] = (float (*)[D_DIM])s_router;
    float (*lg)[E_NUM] = (float (*)[E_NUM])(s_router + 8 * D_DIM);

    const int tid = threadIdx.x;
    const int t0 = blockIdx.x * 8;

    // cooperative load of 8 token rows
    const float4* xg = (const float4*)(x + (size_t)t0 * D_DIM);
    float4* xs4 = (float4*)xs;
    for (int i = tid; i < 8 * D_DIM / 4; i += 256) xs4[i] = xg[i];
    __syncthreads();

    const int warp = tid >> 5, lane = tid & 31;

    // each warp computes 8 experts for all 8 tokens
    for (int j = 0; j < 8; j++) {
        const int e = warp * 8 + j;
        const float4* gr = (const float4*)(gate_w + (size_t)e * D_DIM);
        float acc[8];
#pragma unroll
        for (int t = 0; t < 8; t++) acc[t] = 0.f;
        for (int d4 = lane; d4 < D_DIM / 4; d4 += 32) {
            float4 g = gr[d4];
#pragma unroll
            for (int t = 0; t < 8; t++) {
                float4 xv = *(const float4*)(&xs[t][d4 * 4]);
                acc[t] = fmaf(g.x, xv.x, fmaf(g.y, xv.y,
                          fmaf(g.z, xv.z, fmaf(g.w, xv.w, acc[t]))));
            }
        }
#pragma unroll
        for (int off = 16; off > 0; off >>= 1)
#pragma unroll
            for (int t = 0; t < 8; t++)
                acc[t] += __shfl_xor_sync(0xffffffffu, acc[t], off);
        if (lane == 0)
#pragma unroll
            for (int t = 0; t < 8; t++) lg[t][e] = acc[t];
    }
    __syncthreads();

    // warp w handles token w: softmax (fp32), top-8 (lower index wins ties), renorm
    {
        const int t = warp;
        float v0 = lg[t][lane];
        float v1 = lg[t][lane + 32];
        float m = fmaxf(v0, v1);
#pragma unroll
        for (int off = 16; off > 0; off >>= 1)
            m = fmaxf(m, __shfl_xor_sync(0xffffffffu, m, off));
        float e0 = expf(v0 - m), e1 = expf(v1 - m);
        float s = e0 + e1;
#pragma unroll
        for (int off = 16; off > 0; off >>= 1)
            s += __shfl_xor_sync(0xffffffffu, s, off);
        float p0 = e0 / s, p1 = e1 / s;

        float selw[TOPK];
        int   sele[TOPK];
#pragma unroll
        for (int k = 0; k < TOPK; k++) {
            float bv; int bi;
            if (p0 >= p1) { bv = p0; bi = lane; }
            else          { bv = p1; bi = lane + 32; }
#pragma unroll
            for (int off = 16; off > 0; off >>= 1) {
                float ov = __shfl_xor_sync(0xffffffffu, bv, off);
                int   oi = __shfl_xor_sync(0xffffffffu, bi, off);
                if (ov > bv || (ov == bv && oi < bi)) { bv = ov; bi = oi; }
            }
            selw[k] = bv; sele[k] = bi;
            if (bi == lane)      p0 = -1.f;
            if (bi == lane + 32) p1 = -1.f;
        }
        float wsum = 0.f;
#pragma unroll
        for (int k = 0; k < TOPK; k++) wsum += selw[k];

        if (lane == 0) {
            const int tok = t0 + t;
#pragma unroll
            for (int k = 0; k < TOPK; k++) {
                const int e = sele[k];
                const int pos = atomicAdd(&g_counts[e], 1);
                if (pos < CAP) {
                    g_slot_token[e * CAP + pos]  = tok;
                    g_slot_weight[e * CAP + pos] = selw[k] / wsum;
                }
            }
        }
    }
}

// ---------------- kernel 3: grouped GEMM1 (gate+up fused, SwiGLU) ----------
// BM=64, BN=64 (over H), BK=16; 256 threads; 4x4 microtile; dual accumulators.
__global__ __launch_bounds__(256) void gemm1_kernel(
    const float* __restrict__ x,
    const float* __restrict__ Wg,   // [E, D, H]
    const float* __restrict__ Wu)   // [E, D, H]
{
    const int e = blockIdx.z;
    const int n_e = min(g_counts[e], CAP);
    const int row0 = blockIdx.y * 64;
    if (row0 >= n_e) return;
    const int col0 = blockIdx.x * 64;

    __shared__ float Xs[16][68];
    __shared__ float Gs[16][68];
    __shared__ float Us[16][68];
    __shared__ int   stok[64];

    const int tid = threadIdx.x;
    if (tid < 64) {
        const int r = row0 + tid;
        stok[tid] = (r < n_e) ? g_slot_token[e * CAP + r] : -1;
    }
    __syncthreads();

    const int ty = tid >> 4, tx = tid & 15;
    float accg[4][4] = {}, accu[4][4] = {};

    // X load mapping: one float4 per thread
    const int lr = tid >> 2;            // 0..63 (local row)
    const int lc = (tid & 3) * 4;       // 0,4,8,12 (k offset)
    const int tokr = stok[lr];
    const float* xrow = (tokr >= 0) ? (x + (size_t)tokr * D_DIM) : x;
    const bool xok = (tokr >= 0);

    // W load mapping: one float4 per thread per matrix
    const int wk = tid >> 4;            // 0..15 (k)
    const int wn = (tid & 15) * 4;      // 0..60 (n)
    const float* wg_base = Wg + (size_t)e * D_DIM * H_DIM + col0 + wn;
    const float* wu_base = Wu + (size_t)e * D_DIM * H_DIM + col0 + wn;

    for (int kk = 0; kk < D_DIM; kk += 16) {
        float4 xv = make_float4(0.f, 0.f, 0.f, 0.f);
        if (xok) xv = *(const float4*)(xrow + kk + lc);
        float4 gv = *(const float4*)(wg_base + (size_t)(kk + wk) * H_DIM);
        float4 uv = *(const float4*)(wu_base + (size_t)(kk + wk) * H_DIM);

        __syncthreads();
        Xs[lc + 0][lr] = xv.x; Xs[lc + 1][lr] = xv.y;
        Xs[lc + 2][lr] = xv.z; Xs[lc + 3][lr] = xv.w;
        *(float4*)&Gs[wk][wn] = gv;
        *(float4*)&Us[wk][wn] = uv;
        __syncthreads();

#pragma unroll
        for (int k = 0; k < 16; k++) {
            float4 a  = *(const float4*)&Xs[k][ty * 4];
            float4 bg = *(const float4*)&Gs[k][tx * 4];
            float4 bu = *(const float4*)&Us[k][tx * 4];
            float av[4]  = {a.x, a.y, a.z, a.w};
            float bgv[4] = {bg.x, bg.y, bg.z, bg.w};
            float buv[4] = {bu.x, bu.y, bu.z, bu.w};
#pragma unroll
            for (int i = 0; i < 4; i++)
#pragma unroll
                for (int j = 0; j < 4; j++) {
                    accg[i][j] = fmaf(av[i], bgv[j], accg[i][j]);
                    accu[i][j] = fmaf(av[i], buv[j], accu[i][j]);
                }
        }
    }

    // epilogue: SwiGLU, store to act scratch
#pragma unroll
    for (int i = 0; i < 4; i++) {
        const int r = row0 + ty * 4 + i;
        if (r >= n_e) continue;
        float* arow = g_act + ((size_t)e * CAP + r) * H_DIM + col0 + tx * 4;
        float4 o;
        float g, u;
        g = accg[i][0]; u = accu[i][0]; o.x = (g / (1.f + expf(-g))) * u;
        g = accg[i][1]; u = accu[i][1]; o.y = (g / (1.f + expf(-g))) * u;
        g = accg[i][2]; u = accu[i][2]; o.z = (g / (1.f + expf(-g))) * u;
        g = accg[i][3]; u = accu[i][3]; o.w = (g / (1.f + expf(-g))) * u;
        *(float4*)arow = o;
    }
}

// ---------------- kernel 4: grouped GEMM2 (down proj) + weighted scatter ---
// BM=64, BN=128 (over D), BK=16; 256 threads; 4x8 microtile; atomicAdd combine.
__global__ __launch_bounds__(256) void gemm2_kernel(
    const float* __restrict__ Wd,   // [E, H, D]
    float* __restrict__ out)
{
    const int e = blockIdx.z;
    const int n_e = min(g_counts[e], CAP);
    const int row0 = blockIdx.y * 64;
    if (row0 >= n_e) return;
    const int col0 = blockIdx.x * 128;

    __shared__ float As[16][68];
    __shared__ float Bs[16][132];
    __shared__ int   stok[64];
    __shared__ float sw[64];

    const int tid = threadIdx.x;
    if (tid < 64) {
        const int r = row0 + tid;
        stok[tid] = (r < n_e) ? g_slot_token[e * CAP + r] : 0;
        sw[tid]   = (r < n_e) ? g_slot_weight[e * CAP + r] : 0.f;
    }

    const int ty = tid >> 4, tx = tid & 15;
    float acc[4][8] = {};

    const int lr = tid >> 2;
    const int lc = (tid & 3) * 4;
    const bool arow_ok = (row0 + lr) < n_e;
    const float* arow = g_act + ((size_t)e * CAP + row0 + lr) * H_DIM;
    const float* wd_base = Wd + (size_t)e * H_DIM * D_DIM + col0;

    for (int kk = 0; kk < H_DIM; kk += 16) {
        float4 av = make_float4(0.f, 0.f, 0.f, 0.f);
        if (arow_ok) av = *(const float4*)(arow + kk + lc);
        float4 bvv[2];
#pragma unroll
        for (int it = 0; it < 2; it++) {
            const int idx = tid + it * 256;   // 0..511
            const int bk = idx >> 5;          // 0..15
            const int bn = (idx & 31) * 4;    // 0..124
            bvv[it] = *(const float4*)(wd_base + (size_t)(kk + bk) * D_DIM + bn);
        }

        __syncthreads();
        As[lc + 0][lr] = av.x; As[lc + 1][lr] = av.y;
        As[lc + 2][lr] = av.z; As[lc + 3][lr] = av.w;
#pragma unroll
        for (int it = 0; it < 2; it++) {
            const int idx = tid + it * 256;
            const int bk = idx >> 5;
            const int bn = (idx & 31) * 4;
            *(float4*)&Bs[bk][bn] = bvv[it];
        }
        __syncthreads();

#pragma unroll
        for (int k = 0; k < 16; k++) {
            float4 a  = *(const float4*)&As[k][ty * 4];
            float4 b0 = *(const float4*)&Bs[k][tx * 8];
            float4 b1 = *(const float4*)&Bs[k][tx * 8 + 4];
            float avr[4] = {a.x, a.y, a.z, a.w};
            float bvr[8] = {b0.x, b0.y, b0.z, b0.w, b1.x, b1.y, b1.z, b1.w};
#pragma unroll
            for (int i = 0; i < 4; i++)
#pragma unroll
                for (int j = 0; j < 8; j++)
                    acc[i][j] = fmaf(avr[i], bvr[j], acc[i][j]);
        }
    }

    // epilogue: weighted scatter-add into out
#pragma unroll
    for (int i = 0; i < 4; i++) {
        const int r = row0 + ty * 4 + i;
        if (r >= n_e) continue;
        const int t = stok[ty * 4 + i];
        const float w = sw[ty * 4 + i];
        float* orow = out + (size_t)t * D_DIM + col0 + tx * 8;
#pragma unroll
        for (int j = 0; j < 8; j++)
            atomicAdd(&orow[j], w * acc[i][j]);
    }
}

// ---------------- launcher --------------------------------------------------
extern "C" void kernel_launch(void* const* d_in, const int* in_sizes, int n_in,
                              void* d_out, int out_size)
{
    const float* x      = (const float*)d_in[0];
    const float* gate_w = (const float*)d_in[1];
    const float* W_gate = (const float*)d_in[2];
    const float* W_up   = (const float*)d_in[3];
    const float* W_down = (const float*)d_in[4];
    float* out = (float*)d_out;

    const int router_smem = 8 * D_DIM * 4 + 8 * E_NUM * 4;  // 51200 bytes
    cudaFuncSetAttribute(router_kernel,
                         cudaFuncAttributeMaxDynamicSharedMemorySize,
                         router_smem);

    zero_kernel<<<1024, 256>>>(out);
    router_kernel<<<T_NUM / 8, 256, router_smem>>>(x, gate_w);
    gemm1_kernel<<<dim3(H_DIM / 64, CAP / 64, E_NUM), 256>>>(x, W_gate, W_up);
    gemm2_kernel<<<dim3(D_DIM / 128, CAP / 64, E_NUM), 256>>>(W_down, out);
}